// round 15
// baseline (speedup 1.0000x reference)
#include <cuda_runtime.h>
#include <cstdint>
#define DI __device__ __forceinline__
typedef unsigned long long u64;

__device__ __align__(256) float g_bufA[33554432];
__device__ __align__(256) float g_bufB[16777216];
__device__ __align__(256) float g_pool4[4194304];
__device__ __align__(256) float g_rows[4194304];
__device__ __align__(256) float g_pre[2][8388608];
__device__ __align__(256) float g_hs[2][2097152];
__device__ __align__(256) float g_cenc[2][32768];
__device__ __align__(256) float g_memory[4194304];
__device__ __align__(256) float g_keys[4194304];
__device__ __align__(256) float g_zpart[524288];
__device__ __align__(256) float g_qpart2[16384];
__device__ __align__(256) float g_scores[8192];
__device__ __align__(256) float g_ctx[8192];
__device__ __align__(256) float g_lpart[65536];
__device__ __align__(256) float g_h2[16384];
__device__ __align__(256) float g_cdec[8192];
__device__ __align__(256) float g_wdecF[2260992];
__device__ __align__(256) float g_wlogF[524288];
__device__ __align__(256) float g_woutP[262144];
__device__ unsigned g_cnt = 0;
__device__ unsigned g_gen = 0;

DI float sigm(float x) { return __fdividef(1.f, 1.f + __expf(-x)); }
DI float tanh_(float x) { float t = __expf(2.f * x); return 1.f - __fdividef(2.f, t + 1.f); }
DI float tanha(float x) { float y; asm("tanh.approx.f32 %0,%1;" : "=f"(y) : "f"(x)); return y; }

DI u64 pk2(float a, float b) { u64 r; asm("mov.b64 %0,{%1,%2};" : "=l"(r) : "f"(a), "f"(b)); return r; }
DI void fm2(u64& d, u64 a, u64 b) { asm("fma.rn.f32x2 %0,%1,%2,%3;" : "=l"(d) : "l"(a), "l"(b), "l"(d)); }
DI float2 up2(u64 v) { float2 r; asm("mov.b64 {%0,%1},%2;" : "=f"(r.x), "=f"(r.y) : "l"(v)); return r; }

DI void gridbar() {
    __syncthreads();
    if (threadIdx.x == 0) {
        unsigned gen;
        asm volatile("ld.acquire.gpu.global.u32 %0, [%1];" : "=r"(gen) : "l"(&g_gen));
        asm volatile("red.release.gpu.global.add.u32 [%0], %1;" :: "l"(&g_cnt), "r"(1u));
        if (blockIdx.x == 0) {
            unsigned c;
            do {
                asm volatile("ld.acquire.gpu.global.u32 %0, [%1];" : "=r"(c) : "l"(&g_cnt));
            } while (c < gridDim.x);
            asm volatile("st.relaxed.gpu.global.u32 [%0], %1;" :: "l"(&g_cnt), "r"(0u));
            asm volatile("red.release.gpu.global.add.u32 [%0], %1;" :: "l"(&g_gen), "r"(1u));
        } else {
            unsigned g2;
            do {
                asm volatile("ld.acquire.gpu.global.u32 %0, [%1];" : "=r"(g2) : "l"(&g_gen));
            } while (g2 == gen);
        }
    }
    __syncthreads();
}

__global__ void k_init() {
    int i = blockIdx.x * 256 + threadIdx.x;  // grid 256
    if (i < 32768) { g_cenc[0][i] = 0.f; g_cenc[1][i] = 0.f; }
    if (i < 16384) g_h2[i] = 0.f;
    if (i < 8192)  { g_cdec[i] = 0.f; g_ctx[i] = 0.f; }
}

__global__ void k_padW(const float* __restrict__ Wout) {
    int i = blockIdx.x * 256 + threadIdx.x;
    int k = i >> 9, c = i & 511;
    g_woutP[i] = (c < 504) ? Wout[k * 504 + c] : 0.f;
}

// 64x64-tile GEMM for the small fold matrices: C = A@B (+addm)
__global__ void __launch_bounds__(256) k_gemm64(const float* __restrict__ A,
        const float* __restrict__ B, const float* __restrict__ addm,
        float* __restrict__ C, int N, int K) {
    __shared__ float As[16][68];
    __shared__ float Bs[16][64];
    int bm = blockIdx.y << 6, bn = blockIdx.x << 6, tid = threadIdx.x;
    int tr = tid >> 4, tc = tid & 15;
    int lm = tid >> 2, lk = (tid & 3) << 2;
    int bkn = (tid & 15) << 2, bkk = tid >> 4;
    float acc[16];
#pragma unroll
    for (int i = 0; i < 16; i++) acc[i] = 0.f;
    for (int k0 = 0; k0 < K; k0 += 16) {
        float4 av = *(const float4*)&A[(size_t)(bm + lm) * K + k0 + lk];
        As[lk][lm] = av.x; As[lk + 1][lm] = av.y;
        As[lk + 2][lm] = av.z; As[lk + 3][lm] = av.w;
        *(float4*)&Bs[bkk][bkn] = *(const float4*)&B[(size_t)(k0 + bkk) * N + bn + bkn];
        __syncthreads();
#pragma unroll
        for (int kk = 0; kk < 16; kk++) {
            float4 a = *(const float4*)&As[kk][tr << 2];
            float4 b = *(const float4*)&Bs[kk][tc << 2];
            acc[0]  += a.x * b.x; acc[1]  += a.x * b.y; acc[2]  += a.x * b.z; acc[3]  += a.x * b.w;
            acc[4]  += a.y * b.x; acc[5]  += a.y * b.y; acc[6]  += a.y * b.z; acc[7]  += a.y * b.w;
            acc[8]  += a.z * b.x; acc[9]  += a.z * b.y; acc[10] += a.z * b.z; acc[11] += a.z * b.w;
            acc[12] += a.w * b.x; acc[13] += a.w * b.y; acc[14] += a.w * b.z; acc[15] += a.w * b.w;
        }
        __syncthreads();
    }
    int orow = bm + (tr << 2), ocol = bn + (tc << 2);
#pragma unroll
    for (int i = 0; i < 4; i++) {
        const float* ap = addm ? &addm[(size_t)(orow + i) * N + ocol] : 0;
#pragma unroll
        for (int j = 0; j < 4; j++)
            C[(size_t)(orow + i) * N + ocol + j] =
                acc[i * 4 + j] + (ap ? ap[j] : 0.f);
    }
}

// fused conv1 (3x3, Cin=1, Cout=64) + 2x2 maxpool
__global__ void __launch_bounds__(256) k_conv1pool(const float* __restrict__ in,
        const float* __restrict__ wt, const float* __restrict__ bias,
        float* __restrict__ out) {
    __shared__ float ws[9][64];
    __shared__ float bs[64];
    int tid = threadIdx.x;
    if (tid < 64) bs[tid] = bias[tid];
    for (int i = tid; i < 576; i += 256) ws[i >> 6][i & 63] = wt[i];
    __syncthreads();
    int pg = blockIdx.x * 64 + (tid >> 2);
    int c0 = (tid & 3) * 16;
    int wp = pg & 255, hp = (pg >> 8) & 31, b = pg >> 13;
    int h0 = hp * 2, w0 = wp * 2;
    float patch[4][4];
#pragma unroll
    for (int dy = 0; dy < 4; dy++) {
        int h = h0 + dy - 1;
#pragma unroll
        for (int dx = 0; dx < 4; dx++) {
            int w = w0 + dx - 1;
            patch[dy][dx] = (h >= 0 && h < 64 && w >= 0 && w < 512)
                            ? in[(size_t)(b * 64 + h) * 512 + w] : 0.f;
        }
    }
    float* op = &out[((size_t)(b * 32 + hp) * 256 + wp) * 64 + c0];
#pragma unroll
    for (int co = 0; co < 16; co++) {
        float w9[9];
#pragma unroll
        for (int t = 0; t < 9; t++) w9[t] = ws[t][c0 + co];
        float best = -1e30f;
#pragma unroll
        for (int dy = 0; dy < 2; dy++)
#pragma unroll
            for (int dx = 0; dx < 2; dx++) {
                float s = 0.f;
#pragma unroll
                for (int kh = 0; kh < 3; kh++)
#pragma unroll
                    for (int kw = 0; kw < 3; kw++)
                        s += patch[dy + kh][dx + kw] * w9[kh * 3 + kw];
                best = fmaxf(best, s);
            }
        op[co] = fmaxf(best + bs[c0 + co], 0.f);
    }
}

// big conv: 128x128 tile, 8x8 micro, f32x2, software-pipelined k-tiles
__global__ void __launch_bounds__(256) k_conv128(const float* __restrict__ in,
        const float* __restrict__ wt, const float* __restrict__ bias,
        float* __restrict__ out, int H, int W, int Cin, int Cout) {
    __shared__ float As[16][132];
    __shared__ float Bs[16][132];
    int bm = blockIdx.y << 7, bn = blockIdx.x << 7, tid = threadIdx.x;
    int lm = tid >> 1, kh8 = (tid & 1) << 3;
    int m = bm + lm;
    int wq = m % W; int tmp = m / W; int hq = tmp % H; int nq = tmp / H;
    int bkk = tid >> 5, bkn = (tid & 31) << 2;
    int cr = (tid >> 4) << 3, cc = (tid & 15) << 3;
    int nct = Cin >> 4, ntiles = 9 * nct;
    u64 acc2[4][8];
#pragma unroll
    for (int i = 0; i < 4; i++)
#pragma unroll
        for (int j = 0; j < 8; j++) acc2[i][j] = pk2(0.f, 0.f);

    float4 a0, a1, b0, b1;
    {
        // load tile 0
        int ih = hq - 1, iw = wq - 1;
        bool ok = (ih >= 0) && (iw >= 0);
        const float* ibase = in + (((size_t)nq * H + ih) * W + iw) * Cin + kh8;
        a0 = ok ? *(const float4*)ibase : make_float4(0.f, 0.f, 0.f, 0.f);
        a1 = ok ? *(const float4*)(ibase + 4) : make_float4(0.f, 0.f, 0.f, 0.f);
        const float* wbase = wt + bn + bkn;
        b0 = *(const float4*)(wbase + (size_t)bkk * Cout);
        b1 = *(const float4*)(wbase + (size_t)(bkk + 8) * Cout);
    }
    for (int kt = 0; kt < ntiles; kt++) {
        __syncthreads();
        As[kh8 + 0][lm] = a0.x; As[kh8 + 1][lm] = a0.y;
        As[kh8 + 2][lm] = a0.z; As[kh8 + 3][lm] = a0.w;
        As[kh8 + 4][lm] = a1.x; As[kh8 + 5][lm] = a1.y;
        As[kh8 + 6][lm] = a1.z; As[kh8 + 7][lm] = a1.w;
        *(float4*)&Bs[bkk][bkn] = b0;
        *(float4*)&Bs[bkk + 8][bkn] = b1;
        __syncthreads();
        if (kt + 1 < ntiles) {
            int k2 = kt + 1;
            int khkw = k2 / nct, c0 = (k2 - khkw * nct) << 4;
            int kh = khkw / 3, kw = khkw - kh * 3;
            int ih = hq + kh - 1, iw = wq + kw - 1;
            bool ok = (ih >= 0) && (ih < H) && (iw >= 0) && (iw < W);
            const float* ibase = in + (((size_t)nq * H + ih) * W + iw) * Cin + kh8 + c0;
            a0 = ok ? *(const float4*)ibase : make_float4(0.f, 0.f, 0.f, 0.f);
            a1 = ok ? *(const float4*)(ibase + 4) : make_float4(0.f, 0.f, 0.f, 0.f);
            const float* wbase = wt + (size_t)khkw * Cin * Cout + bn + bkn;
            b0 = *(const float4*)(wbase + (size_t)(c0 + bkk) * Cout);
            b1 = *(const float4*)(wbase + (size_t)(c0 + bkk + 8) * Cout);
        }
#pragma unroll
        for (int kk = 0; kk < 16; kk++) {
            float4 av0 = *(const float4*)&As[kk][cr];
            float4 av1 = *(const float4*)&As[kk][cr + 4];
            u64 ap[4] = { pk2(av0.x, av0.y), pk2(av0.z, av0.w),
                          pk2(av1.x, av1.y), pk2(av1.z, av1.w) };
            float4 c0v = *(const float4*)&Bs[kk][cc];
            float4 c1v = *(const float4*)&Bs[kk][cc + 4];
            u64 bd[8] = { pk2(c0v.x, c0v.x), pk2(c0v.y, c0v.y), pk2(c0v.z, c0v.z),
                          pk2(c0v.w, c0v.w), pk2(c1v.x, c1v.x), pk2(c1v.y, c1v.y),
                          pk2(c1v.z, c1v.z), pk2(c1v.w, c1v.w) };
#pragma unroll
            for (int ip = 0; ip < 4; ip++)
#pragma unroll
                for (int j = 0; j < 8; j++) fm2(acc2[ip][j], ap[ip], bd[j]);
        }
    }
#pragma unroll
    for (int ip = 0; ip < 4; ip++) {
        float* op0 = &out[(size_t)(bm + cr + 2 * ip) * Cout + bn + cc];
        float* op1 = op0 + Cout;
#pragma unroll
        for (int j = 0; j < 8; j++) {
            float2 v = up2(acc2[ip][j]);
            float bb = bias[bn + cc + j];
            op0[j] = fmaxf(v.x + bb, 0.f);
            op1[j] = fmaxf(v.y + bb, 0.f);
        }
    }
}

// big GEMM: C = A@B (+bias). 128x128 tile, f32x2, software-pipelined
__global__ void __launch_bounds__(256) k_gemm128(const float* __restrict__ A,
        const float* __restrict__ B, const float* __restrict__ bias,
        float* __restrict__ C, int N, int K) {
    __shared__ float As[16][132];
    __shared__ float Bs[16][132];
    int bm = blockIdx.y << 7, bn = blockIdx.x << 7, tid = threadIdx.x;
    int lm = tid >> 1, kh8 = (tid & 1) << 3;
    int bkk = tid >> 5, bkn = (tid & 31) << 2;
    int cr = (tid >> 4) << 3, cc = (tid & 15) << 3;
    const float* arow = A + (size_t)(bm + lm) * K + kh8;
    const float* bcol = B + bn + bkn;
    int ntiles = K >> 4;
    u64 acc2[4][8];
#pragma unroll
    for (int i = 0; i < 4; i++)
#pragma unroll
        for (int j = 0; j < 8; j++) acc2[i][j] = pk2(0.f, 0.f);
    float4 a0 = *(const float4*)arow;
    float4 a1 = *(const float4*)(arow + 4);
    float4 b0 = *(const float4*)(bcol + (size_t)bkk * N);
    float4 b1 = *(const float4*)(bcol + (size_t)(bkk + 8) * N);
    for (int kt = 0; kt < ntiles; kt++) {
        __syncthreads();
        As[kh8 + 0][lm] = a0.x; As[kh8 + 1][lm] = a0.y;
        As[kh8 + 2][lm] = a0.z; As[kh8 + 3][lm] = a0.w;
        As[kh8 + 4][lm] = a1.x; As[kh8 + 5][lm] = a1.y;
        As[kh8 + 6][lm] = a1.z; As[kh8 + 7][lm] = a1.w;
        *(float4*)&Bs[bkk][bkn] = b0;
        *(float4*)&Bs[bkk + 8][bkn] = b1;
        __syncthreads();
        if (kt + 1 < ntiles) {
            int k0 = (kt + 1) << 4;
            a0 = *(const float4*)(arow + k0);
            a1 = *(const float4*)(arow + k0 + 4);
            b0 = *(const float4*)(bcol + (size_t)(k0 + bkk) * N);
            b1 = *(const float4*)(bcol + (size_t)(k0 + bkk + 8) * N);
        }
#pragma unroll
        for (int kk = 0; kk < 16; kk++) {
            float4 av0 = *(const float4*)&As[kk][cr];
            float4 av1 = *(const float4*)&As[kk][cr + 4];
            u64 ap[4] = { pk2(av0.x, av0.y), pk2(av0.z, av0.w),
                          pk2(av1.x, av1.y), pk2(av1.z, av1.w) };
            float4 c0v = *(const float4*)&Bs[kk][cc];
            float4 c1v = *(const float4*)&Bs[kk][cc + 4];
            u64 bd[8] = { pk2(c0v.x, c0v.x), pk2(c0v.y, c0v.y), pk2(c0v.z, c0v.z),
                          pk2(c0v.w, c0v.w), pk2(c1v.x, c1v.x), pk2(c1v.y, c1v.y),
                          pk2(c1v.z, c1v.z), pk2(c1v.w, c1v.w) };
#pragma unroll
            for (int ip = 0; ip < 4; ip++)
#pragma unroll
                for (int j = 0; j < 8; j++) fm2(acc2[ip][j], ap[ip], bd[j]);
        }
    }
#pragma unroll
    for (int ip = 0; ip < 4; ip++) {
        float* op0 = &C[(size_t)(bm + cr + 2 * ip) * N + bn + cc];
        float* op1 = op0 + N;
#pragma unroll
        for (int j = 0; j < 8; j++) {
            float2 v = up2(acc2[ip][j]);
            float bb = bias ? bias[bn + cc + j] : 0.f;
            op0[j] = v.x + bb;
            op1[j] = v.y + bb;
        }
    }
}

__global__ void k_pool(const float* __restrict__ in, float* __restrict__ out,
                       int B, int H, int W, int C) {
    int Ho = H >> 1, Wo = W >> 1, c4g = C >> 2;
    int total = B * Ho * Wo * c4g;
    int i = blockIdx.x * 256 + threadIdx.x;
    if (i >= total) return;
    int c4 = (i % c4g) << 2;
    int rem = i / c4g;
    int w = rem % Wo; rem /= Wo;
    int h = rem % Ho; int b = rem / Ho;
    const float* p0 = &in[(((size_t)b * H + 2 * h) * W + 2 * w) * C + c4];
    const float* p1 = p0 + (size_t)W * C;
    float4 a = *(const float4*)p0, b4 = *(const float4*)(p0 + C);
    float4 c = *(const float4*)p1, d = *(const float4*)(p1 + C);
    float4 r;
    r.x = fmaxf(fmaxf(a.x, b4.x), fmaxf(c.x, d.x));
    r.y = fmaxf(fmaxf(a.y, b4.y), fmaxf(c.y, d.y));
    r.z = fmaxf(fmaxf(a.z, b4.z), fmaxf(c.z, d.z));
    r.w = fmaxf(fmaxf(a.w, b4.w), fmaxf(c.w, d.w));
    *(float4*)&out[(((size_t)b * Ho + h) * Wo + w) * C + c4] = r;
}

__global__ void k_make_rows() {
    int i = blockIdx.x * 256 + threadIdx.x;
    if (i >= 1048576) return;
    int c4 = (i & 127) << 2;
    int m = i >> 7;
    int n = m >> 6, wp = m & 63;
    *(float4*)&g_rows[((size_t)wp * 128 + n) * 512 + c4] =
        *(const float4*)&g_pool4[(size_t)m * 512 + c4];
}

// persistent bidirectional LSTM: 128 units (8 rows each) = 1 wave per step
__global__ void __launch_bounds__(256) k_lstm_all(const float* __restrict__ Wfw,
                                                  const float* __restrict__ Wbw) {
    __shared__ float Hs[256][9];
    __shared__ float Zs[4][8][64];
    int t = threadIdx.x;
    for (int s = 0; s < 64; s++) {
        for (int vb = blockIdx.x; vb < 128; vb += gridDim.x) {
            int dir = vb >> 6, rg = (vb >> 2) & 15, dg = vb & 3;
            const float* W = dir ? Wbw : Wfw;
            int tx = dir ? (63 - s) : s;
            int n0 = rg << 3;
            int dl = t & 63, g = t >> 6;
            int d = (dg << 6) + dl;
            float a[8];
#pragma unroll
            for (int r = 0; r < 8; r++) a[r] = 0.f;
            if (s > 0) {
                int txp = dir ? (64 - s) : (s - 1);
                const float* hprev = &g_hs[dir][(size_t)txp * 32768];
                for (int i = t; i < 2048; i += 256) {
                    int r = i >> 8, k = i & 255;
                    Hs[k][r] = hprev[(n0 + r) * 256 + k];
                }
                __syncthreads();
                const float* wp = &W[(size_t)512 * 1024 + g * 256 + d];
#pragma unroll 8
                for (int k = 0; k < 256; k++) {
                    float w = wp[(size_t)k * 1024];
#pragma unroll
                    for (int r = 0; r < 8; r++) a[r] += Hs[k][r] * w;
                }
            }
#pragma unroll
            for (int r = 0; r < 8; r++) Zs[g][r][dl] = a[r];
            __syncthreads();
            for (int idx = t; idx < 512; idx += 256) {
                int r = idx >> 6, dl2 = idx & 63;
                int dd = (dg << 6) + dl2;
                const float* pre = &g_pre[dir][((size_t)tx * 128 + n0 + r) * 1024];
                float zi = Zs[0][r][dl2] + pre[dd];
                float zj = Zs[1][r][dl2] + pre[256 + dd];
                float zf = Zs[2][r][dl2] + pre[512 + dd];
                float zo = Zs[3][r][dl2] + pre[768 + dd];
                int ci = (n0 + r) * 256 + dd;
                float c = g_cenc[dir][ci];
                c = sigm(zf + 1.f) * c + sigm(zi) * tanh_(zj);
                g_cenc[dir][ci] = c;
                g_hs[dir][(size_t)tx * 32768 + ci] = sigm(zo) * tanh_(c);
            }
            __syncthreads();
        }
        gridbar();
    }
}

__global__ void k_make_memory() {
    int i = blockIdx.x * 256 + threadIdx.x;
    if (i >= 1048576) return;
    int c4 = (i & 127) << 2;
    int li = i >> 7;
    int b = li >> 9, l = li & 511;
    int hp = l >> 6, wp = l & 63;
    int n = b * 8 + hp;
    float4 v = (c4 < 256)
        ? *(const float4*)&g_hs[0][((size_t)wp * 128 + n) * 256 + c4]
        : *(const float4*)&g_hs[1][((size_t)wp * 128 + n) * 256 + (c4 - 256)];
    *(float4*)&g_memory[(size_t)li * 512 + c4] = v;
}

// persistent decoder: 150 steps, 4 gridbars/step, const-stream prefetch past barriers
__global__ void __launch_bounds__(256) k_decoder(
    const float* __restrict__ emb, const int* __restrict__ labels,
    const float* __restrict__ bdec, const float* __restrict__ Wq,
    const float* __restrict__ v_att, const float* __restrict__ bout,
    float* __restrict__ out) {
    __shared__ float sp[2304];
    int tid = threadIdx.x;
    int bid = blockIdx.x;
    for (int st = 0; st <= 150; st++) {
        int hp = (st + 1) & 1;
        // ---- slot A: P1 z partials (128u) || P7a logits partial (16u) ----
        for (int vb = bid; vb < 144; vb += gridDim.x) {
            if (vb < 128) {
                if (st >= 150) continue;
                int cb = vb & 7, kc = vb >> 3, k0 = kc * 69;
                for (int i = tid; i < 1104; i += 256) {
                    int r = i / 69, k = i - r * 69;
                    int kg = k0 + k;
                    float v;
                    if (kg < 80) v = emb[labels[r * 151 + st] * 80 + kg];
                    else if (kg < 592) v = g_ctx[r * 512 + (kg - 80)];
                    else v = g_h2[hp * 8192 + r * 512 + (kg - 592)];
                    sp[r * 72 + k] = v;
                }
                __syncthreads();
                int c0 = cb * 256 + (tid & 63) * 4;
                int rg = tid >> 6;
                float acc[4][4] = {};
#pragma unroll 16
                for (int kk = 0; kk < 69; kk++) {
                    float4 w = *(const float4*)&g_wdecF[(size_t)(k0 + kk) * 2048 + c0];
#pragma unroll
                    for (int r = 0; r < 4; r++) {
                        float x = sp[(rg * 4 + r) * 72 + kk];
                        acc[r][0] += x * w.x; acc[r][1] += x * w.y;
                        acc[r][2] += x * w.z; acc[r][3] += x * w.w;
                    }
                }
#pragma unroll
                for (int r = 0; r < 4; r++)
                    *(float4*)&g_zpart[(size_t)(kc * 16 + rg * 4 + r) * 2048 + c0] =
                        make_float4(acc[r][0], acc[r][1], acc[r][2], acc[r][3]);
                __syncthreads();
            } else if (st >= 1) {
                int u = vb - 128;
                int cb = u & 1, kc = u >> 1, k0 = kc * 128;
                for (int i = tid; i < 2048; i += 256) {
                    int r = i >> 7, k = i & 127;
                    int kg = k0 + k;
                    float v = (kg < 512) ? g_h2[hp * 8192 + r * 512 + kg]
                                         : g_ctx[r * 512 + (kg - 512)];
                    sp[r * 132 + k] = v;
                }
                __syncthreads();
                int c0 = cb * 256 + (tid & 63) * 4;
                int rg = tid >> 6;
                float acc[4][4] = {};
#pragma unroll 16
                for (int kk = 0; kk < 128; kk++) {
                    float4 w = *(const float4*)&g_wlogF[(size_t)(k0 + kk) * 512 + c0];
#pragma unroll
                    for (int r = 0; r < 4; r++) {
                        float x = sp[(rg * 4 + r) * 132 + kk];
                        acc[r][0] += x * w.x; acc[r][1] += x * w.y;
                        acc[r][2] += x * w.z; acc[r][3] += x * w.w;
                    }
                }
#pragma unroll
                for (int r = 0; r < 4; r++)
                    *(float4*)&g_lpart[(size_t)(kc * 16 + rg * 4 + r) * 512 + c0] =
                        make_float4(acc[r][0], acc[r][1], acc[r][2], acc[r][3]);
                __syncthreads();
            }
        }
        gridbar();
        // ---- slot B: P2 gates+h+qpart (32u) ----
        if (st < 150) {
            for (int vb = bid; vb < 32; vb += gridDim.x) {
                int b = vb >> 1, half = vb & 1, d0 = half * 256;
                int d = d0 + tid;
                float zi = bdec[d], zj = bdec[512 + d], zf = bdec[1024 + d], zo = bdec[1536 + d];
#pragma unroll
                for (int p = 0; p < 16; p++) {
                    const float* zp = &g_zpart[(size_t)(p * 16 + b) * 2048];
                    zi += zp[d]; zj += zp[512 + d]; zf += zp[1024 + d]; zo += zp[1536 + d];
                }
                float c = g_cdec[b * 512 + d];
                c = sigm(zf + 1.f) * c + sigm(zi) * tanh_(zj);
                float h = sigm(zo) * tanh_(c);
                g_cdec[b * 512 + d] = c;
                g_h2[(st & 1) * 8192 + b * 512 + d] = h;
                sp[tid] = h;
                __syncthreads();
                int c4 = (tid & 127) * 4, kh = tid >> 7;
                float4 a = make_float4(0.f, 0.f, 0.f, 0.f);
#pragma unroll 16
                for (int kk = 0; kk < 128; kk++) {
                    int kl = kh * 128 + kk;
                    float x = sp[kl];
                    float4 w = *(const float4*)&Wq[(size_t)(d0 + kl) * 512 + c4];
                    a.x += x * w.x; a.y += x * w.y; a.z += x * w.z; a.w += x * w.w;
                }
                *(float4*)&sp[256 + kh * 512 + c4] = a;
                __syncthreads();
                int base = (half * 16 + b) * 512;
                g_qpart2[base + tid] = sp[256 + tid] + sp[256 + 512 + tid];
                g_qpart2[base + 256 + tid] = sp[256 + 256 + tid] + sp[256 + 768 + tid];
                __syncthreads();
            }
        }
        // prefetch slot-C keys first wave (keys is const; independent of barrier)
        float4 pre[8];
        bool preC = (st < 150) && (bid < 128);
        if (preC) {
            int b = bid >> 3, lg = bid & 7;
            int w = tid >> 5, lane = tid & 31;
#pragma unroll
            for (int j = 0; j < 8; j++) {
                int l = lg * 64 + w * 8 + j;
                pre[j] = *(const float4*)&g_keys[((size_t)b * 512 + l) * 512 + lane * 4];
            }
        }
        gridbar();
        // ---- slot C: P4 scores (128u, tanh.approx) || P7b logits out (8u) ----
        for (int vb = bid; vb < 136; vb += gridDim.x) {
            if (vb < 128) {
                if (st >= 150) continue;
                int b = vb >> 3, lg = vb & 7;
                for (int i = tid; i < 512; i += 256) {
                    sp[i] = g_qpart2[b * 512 + i] + g_qpart2[(16 + b) * 512 + i];
                    sp[512 + i] = v_att[i];
                }
                __syncthreads();
                int w = tid >> 5, lane = tid & 31;
#pragma unroll
                for (int j = 0; j < 8; j++) {
                    int l = lg * 64 + w * 8 + j;
                    const float* kp = &g_keys[((size_t)b * 512 + l) * 512];
                    int d0 = lane * 4;
                    float4 kv0 = (vb == bid) ? pre[j] : *(const float4*)&kp[d0];
                    float acc = tanha(kv0.x + sp[d0]) * sp[512 + d0]
                              + tanha(kv0.y + sp[d0 + 1]) * sp[512 + d0 + 1]
                              + tanha(kv0.z + sp[d0 + 2]) * sp[512 + d0 + 2]
                              + tanha(kv0.w + sp[d0 + 3]) * sp[512 + d0 + 3];
#pragma unroll
                    for (int it = 1; it < 4; it++) {
                        int d = it * 128 + lane * 4;
                        float4 kv = *(const float4*)&kp[d];
                        acc += tanha(kv.x + sp[d]) * sp[512 + d]
                             + tanha(kv.y + sp[d + 1]) * sp[512 + d + 1]
                             + tanha(kv.z + sp[d + 2]) * sp[512 + d + 2]
                             + tanha(kv.w + sp[d + 3]) * sp[512 + d + 3];
                    }
#pragma unroll
                    for (int off = 16; off; off >>= 1) acc += __shfl_down_sync(0xffffffffu, acc, off);
                    if (lane == 0) g_scores[b * 512 + l] = acc;
                }
                __syncthreads();
            } else if (st >= 1) {
                int u = vb - 128;
                if (tid < 252) {
                    int cl = tid % 63, rg = tid / 63;
                    int c = u * 63 + cl;
#pragma unroll
                    for (int i = 0; i < 4; i++) {
                        int b = rg * 4 + i;
                        float s = bout[c];
#pragma unroll
                        for (int p = 0; p < 8; p++) s += g_lpart[(p * 16 + b) * 512 + c];
                        out[((size_t)b * 150 + (st - 1)) * 504 + c] = s;
                    }
                }
            }
        }
        // prefetch slot-D memory first wave (memory is const)
        float4 md[4];
        bool preD = (st < 150) && (bid < 64);
        if (preD) {
            int b = bid >> 2, q4 = bid & 3;
            int rg = tid >> 5;
            int c = q4 * 128 + (tid & 31) * 4;
            const float* mp = &g_memory[((size_t)b * 512 + rg * 64) * 512 + c];
#pragma unroll
            for (int l = 0; l < 4; l++) md[l] = *(const float4*)(mp + (size_t)l * 512);
        }
        gridbar();
        // ---- slot D: P5 softmax + FINAL ctx (64u: b x quarter) ----
        if (st < 150) {
            for (int vb = bid; vb < 64; vb += gridDim.x) {
                int b = vb >> 2, q4 = vb & 3;
                float* sc = sp;
                float* red = sp + 512;
                float* al = sp + 768;
                float* Zs = sp + 1280;
                sc[tid] = g_scores[b * 512 + tid];
                sc[tid + 256] = g_scores[b * 512 + 256 + tid];
                __syncthreads();
                float m = fmaxf(sc[tid], sc[tid + 256]);
                red[tid] = m; __syncthreads();
                for (int s = 128; s; s >>= 1) {
                    if (tid < s) red[tid] = fmaxf(red[tid], red[tid + s]);
                    __syncthreads();
                }
                m = red[0]; __syncthreads();
                float e0 = __expf(sc[tid] - m), e1 = __expf(sc[tid + 256] - m);
                red[tid] = e0 + e1;
                __syncthreads();
                for (int s = 128; s; s >>= 1) {
                    if (tid < s) red[tid] += red[tid + s];
                    __syncthreads();
                }
                float inv = __fdividef(1.f, red[0]);
                __syncthreads();
                al[tid] = e0 * inv; al[tid + 256] = e1 * inv;
                __syncthreads();
                {
                    int rg = tid >> 5;
                    int c = q4 * 128 + (tid & 31) * 4;
                    float4 a = make_float4(0.f, 0.f, 0.f, 0.f);
                    const float* mp = &g_memory[((size_t)b * 512 + rg * 64) * 512 + c];
                    bool usepre = (vb == bid) && preD;
#pragma unroll 16
                    for (int l = 0; l < 64; l++) {
                        float av = al[rg * 64 + l];
                        float4 mv = (usepre && l < 4) ? md[l]
                                    : *(const float4*)(mp + (size_t)l * 512);
                        a.x += av * mv.x; a.y += av * mv.y;
                        a.z += av * mv.z; a.w += av * mv.w;
                    }
                    *(float4*)&Zs[rg * 128 + (tid & 31) * 4] = a;
                }
                __syncthreads();
                if (tid < 128) {
                    float s = 0.f;
#pragma unroll
                    for (int r = 0; r < 8; r++) s += Zs[r * 128 + tid];
                    g_ctx[b * 512 + q4 * 128 + tid] = s;
                }
                __syncthreads();
            }
        }
        gridbar();
    }
}

extern "C" void kernel_launch(void* const* d_in, const int* in_sizes, int n_in,
                              void* d_out, int out_size) {
    (void)in_sizes; (void)out_size;
    int o = n_in - 21;
    const float* inp    = (const float*)d_in[0];
    const int*   labels = (const int*)d_in[1];
    const float* ck1 = (const float*)d_in[o + 0];  const float* cb1 = (const float*)d_in[o + 1];
    const float* ck2 = (const float*)d_in[o + 2];  const float* cb2 = (const float*)d_in[o + 3];
    const float* ck3 = (const float*)d_in[o + 4];  const float* cb3 = (const float*)d_in[o + 5];
    const float* ck4 = (const float*)d_in[o + 6];  const float* cb4 = (const float*)d_in[o + 7];
    const float* Wfw = (const float*)d_in[o + 8];  const float* bfw = (const float*)d_in[o + 9];
    const float* Wbw = (const float*)d_in[o + 10]; const float* bbw = (const float*)d_in[o + 11];
    const float* Wdec = (const float*)d_in[o + 12]; const float* bdec = (const float*)d_in[o + 13];
    const float* Wmem = (const float*)d_in[o + 14]; const float* Wq   = (const float*)d_in[o + 15];
    const float* v_att = (const float*)d_in[o + 16]; const float* Wattn = (const float*)d_in[o + 17];
    const float* Wout = (const float*)d_in[o + 18]; const float* bout = (const float*)d_in[o + 19];
    const float* emb  = (const float*)d_in[o + 20];
    float* out = (float*)d_out;

    void *a_, *b_, *p4_, *r_, *pre_, *mem_, *keys_, *wf_, *wl_, *wp_;
    cudaGetSymbolAddress(&a_, g_bufA);
    cudaGetSymbolAddress(&b_, g_bufB);
    cudaGetSymbolAddress(&p4_, g_pool4);
    cudaGetSymbolAddress(&r_, g_rows);
    cudaGetSymbolAddress(&pre_, g_pre);
    cudaGetSymbolAddress(&mem_, g_memory);
    cudaGetSymbolAddress(&keys_, g_keys);
    cudaGetSymbolAddress(&wf_, g_wdecF);
    cudaGetSymbolAddress(&wl_, g_wlogF);
    cudaGetSymbolAddress(&wp_, g_woutP);
    float* pA = (float*)a_; float* pB = (float*)b_;
    float* pP4 = (float*)p4_; float* pR = (float*)r_;
    float* pPre0 = (float*)pre_; float* pPre1 = pPre0 + 8388608;
    float* pMem = (float*)mem_; float* pKeys = (float*)keys_;
    float* pWdecF = (float*)wf_; float* pWlogF = (float*)wl_;
    float* pWoutP = (float*)wp_;

    cudaMemcpyAsync(pWdecF, Wdec, (size_t)80 * 2048 * sizeof(float),
                    cudaMemcpyDeviceToDevice);
    k_padW<<<1024, 256>>>(Wout);
    k_gemm64<<<dim3(32, 8), 256>>>(Wattn + 512 * 512, Wdec + 80 * 2048,
        (const float*)0, pWdecF + 80 * 2048, 2048, 512);
    k_gemm64<<<dim3(32, 8), 256>>>(Wattn, Wdec + 80 * 2048,
        Wdec + (size_t)592 * 2048, pWdecF + (size_t)592 * 2048, 2048, 512);
    k_gemm64<<<dim3(8, 16), 256>>>(Wattn, pWoutP,
        (const float*)0, pWlogF, 512, 512);

    k_init<<<256, 256>>>();
    k_conv1pool<<<2048, 256>>>(inp, ck1, cb1, pB);
    k_conv128<<<dim3(1, 1024), 256>>>(pB, ck2, cb2, pA, 32, 256, 64, 128);
    k_pool<<<4096, 256>>>(pA, pB, 16, 32, 256, 128);
    k_conv128<<<dim3(2, 256), 256>>>(pB, ck3, cb3, pA, 16, 128, 128, 256);
    k_conv128<<<dim3(4, 256), 256>>>(pA, ck4, cb4, pB, 16, 128, 256, 512);
    k_pool<<<4096, 256>>>(pB, pP4, 16, 16, 128, 512);
    k_make_rows<<<4096, 256>>>();
    k_gemm128<<<dim3(8, 64), 256>>>(pR, Wfw, bfw, pPre0, 1024, 512);
    k_gemm128<<<dim3(8, 64), 256>>>(pR, Wbw, bbw, pPre1, 1024, 512);
    k_lstm_all<<<148, 256>>>(Wfw, Wbw);
    k_make_memory<<<4096, 256>>>();
    k_gemm128<<<dim3(4, 64), 256>>>(pMem, Wmem, (const float*)0, pKeys, 512, 512);
    k_decoder<<<148, 256>>>(emb, labels, bdec, Wq, v_att, bout, out);
}

// round 16
// speedup vs baseline: 1.1006x; 1.1006x over previous
#include <cuda_runtime.h>
#include <cstdint>
#define DI __device__ __forceinline__
typedef unsigned long long u64;

__device__ __align__(256) float g_bufA[33554432];
__device__ __align__(256) float g_bufB[16777216];
__device__ __align__(256) float g_pool4[4194304];
__device__ __align__(256) float g_rows[4194304];
__device__ __align__(256) float g_pre[2][8388608];
__device__ __align__(256) float g_hs[2][2097152];
__device__ __align__(256) float g_cenc[2][32768];
__device__ __align__(256) float g_memory[4194304];
__device__ __align__(256) float g_keys[4194304];
__device__ __align__(256) float g_zpart[524288];
__device__ __align__(256) float g_qpart2[32768];   // 4 q x 16 b x 512
__device__ __align__(256) float g_scores[8192];
__device__ __align__(256) float g_ctx[8192];
__device__ __align__(256) float g_lpart[65536];
__device__ __align__(256) float g_h2[16384];
__device__ __align__(256) float g_cdec[8192];
__device__ __align__(256) float g_wdecF[2260992];
__device__ __align__(256) float g_wlogF[524288];
__device__ __align__(256) float g_woutP[262144];
__device__ unsigned g_cnt = 0;
__device__ unsigned g_gen = 0;

DI float sigm(float x) { return __fdividef(1.f, 1.f + __expf(-x)); }
DI float tanh_(float x) { float t = __expf(2.f * x); return 1.f - __fdividef(2.f, t + 1.f); }
DI float tanha(float x) { float y; asm("tanh.approx.f32 %0,%1;" : "=f"(y) : "f"(x)); return y; }

DI u64 pk2(float a, float b) { u64 r; asm("mov.b64 %0,{%1,%2};" : "=l"(r) : "f"(a), "f"(b)); return r; }
DI void fm2(u64& d, u64 a, u64 b) { asm("fma.rn.f32x2 %0,%1,%2,%3;" : "=l"(d) : "l"(a), "l"(b), "l"(d)); }
DI float2 up2(u64 v) { float2 r; asm("mov.b64 {%0,%1},%2;" : "=f"(r.x), "=f"(r.y) : "l"(v)); return r; }

DI void gridbar() {
    __syncthreads();
    if (threadIdx.x == 0) {
        unsigned gen;
        asm volatile("ld.acquire.gpu.global.u32 %0, [%1];" : "=r"(gen) : "l"(&g_gen));
        asm volatile("red.release.gpu.global.add.u32 [%0], %1;" :: "l"(&g_cnt), "r"(1u));
        if (blockIdx.x == 0) {
            unsigned c;
            do {
                asm volatile("ld.acquire.gpu.global.u32 %0, [%1];" : "=r"(c) : "l"(&g_cnt));
            } while (c < gridDim.x);
            asm volatile("st.relaxed.gpu.global.u32 [%0], %1;" :: "l"(&g_cnt), "r"(0u));
            asm volatile("red.release.gpu.global.add.u32 [%0], %1;" :: "l"(&g_gen), "r"(1u));
        } else {
            unsigned g2;
            do {
                asm volatile("ld.acquire.gpu.global.u32 %0, [%1];" : "=r"(g2) : "l"(&g_gen));
            } while (g2 == gen);
        }
    }
    __syncthreads();
}

__global__ void k_init() {
    int i = blockIdx.x * 256 + threadIdx.x;  // grid 256
    if (i < 32768) { g_cenc[0][i] = 0.f; g_cenc[1][i] = 0.f; }
    if (i < 16384) g_h2[i] = 0.f;
    if (i < 8192)  { g_cdec[i] = 0.f; g_ctx[i] = 0.f; }
}

__global__ void k_padW(const float* __restrict__ Wout) {
    int i = blockIdx.x * 256 + threadIdx.x;
    int k = i >> 9, c = i & 511;
    g_woutP[i] = (c < 504) ? Wout[k * 504 + c] : 0.f;
}

// 64x64-tile GEMM for the small fold matrices: C = A@B (+addm)
__global__ void __launch_bounds__(256) k_gemm64(const float* __restrict__ A,
        const float* __restrict__ B, const float* __restrict__ addm,
        float* __restrict__ C, int N, int K) {
    __shared__ float As[16][68];
    __shared__ float Bs[16][64];
    int bm = blockIdx.y << 6, bn = blockIdx.x << 6, tid = threadIdx.x;
    int tr = tid >> 4, tc = tid & 15;
    int lm = tid >> 2, lk = (tid & 3) << 2;
    int bkn = (tid & 15) << 2, bkk = tid >> 4;
    float acc[16];
#pragma unroll
    for (int i = 0; i < 16; i++) acc[i] = 0.f;
    for (int k0 = 0; k0 < K; k0 += 16) {
        float4 av = *(const float4*)&A[(size_t)(bm + lm) * K + k0 + lk];
        As[lk][lm] = av.x; As[lk + 1][lm] = av.y;
        As[lk + 2][lm] = av.z; As[lk + 3][lm] = av.w;
        *(float4*)&Bs[bkk][bkn] = *(const float4*)&B[(size_t)(k0 + bkk) * N + bn + bkn];
        __syncthreads();
#pragma unroll
        for (int kk = 0; kk < 16; kk++) {
            float4 a = *(const float4*)&As[kk][tr << 2];
            float4 b = *(const float4*)&Bs[kk][tc << 2];
            acc[0]  += a.x * b.x; acc[1]  += a.x * b.y; acc[2]  += a.x * b.z; acc[3]  += a.x * b.w;
            acc[4]  += a.y * b.x; acc[5]  += a.y * b.y; acc[6]  += a.y * b.z; acc[7]  += a.y * b.w;
            acc[8]  += a.z * b.x; acc[9]  += a.z * b.y; acc[10] += a.z * b.z; acc[11] += a.z * b.w;
            acc[12] += a.w * b.x; acc[13] += a.w * b.y; acc[14] += a.w * b.z; acc[15] += a.w * b.w;
        }
        __syncthreads();
    }
    int orow = bm + (tr << 2), ocol = bn + (tc << 2);
#pragma unroll
    for (int i = 0; i < 4; i++) {
        const float* ap = addm ? &addm[(size_t)(orow + i) * N + ocol] : 0;
#pragma unroll
        for (int j = 0; j < 4; j++)
            C[(size_t)(orow + i) * N + ocol + j] =
                acc[i * 4 + j] + (ap ? ap[j] : 0.f);
    }
}

// fused conv1 (3x3, Cin=1, Cout=64) + 2x2 maxpool
__global__ void __launch_bounds__(256) k_conv1pool(const float* __restrict__ in,
        const float* __restrict__ wt, const float* __restrict__ bias,
        float* __restrict__ out) {
    __shared__ float ws[9][64];
    __shared__ float bs[64];
    int tid = threadIdx.x;
    if (tid < 64) bs[tid] = bias[tid];
    for (int i = tid; i < 576; i += 256) ws[i >> 6][i & 63] = wt[i];
    __syncthreads();
    int pg = blockIdx.x * 64 + (tid >> 2);
    int c0 = (tid & 3) * 16;
    int wp = pg & 255, hp = (pg >> 8) & 31, b = pg >> 13;
    int h0 = hp * 2, w0 = wp * 2;
    float patch[4][4];
#pragma unroll
    for (int dy = 0; dy < 4; dy++) {
        int h = h0 + dy - 1;
#pragma unroll
        for (int dx = 0; dx < 4; dx++) {
            int w = w0 + dx - 1;
            patch[dy][dx] = (h >= 0 && h < 64 && w >= 0 && w < 512)
                            ? in[(size_t)(b * 64 + h) * 512 + w] : 0.f;
        }
    }
    float* op = &out[((size_t)(b * 32 + hp) * 256 + wp) * 64 + c0];
#pragma unroll
    for (int co = 0; co < 16; co++) {
        float w9[9];
#pragma unroll
        for (int t = 0; t < 9; t++) w9[t] = ws[t][c0 + co];
        float best = -1e30f;
#pragma unroll
        for (int dy = 0; dy < 2; dy++)
#pragma unroll
            for (int dx = 0; dx < 2; dx++) {
                float s = 0.f;
#pragma unroll
                for (int kh = 0; kh < 3; kh++)
#pragma unroll
                    for (int kw = 0; kw < 3; kw++)
                        s += patch[dy + kh][dx + kw] * w9[kh * 3 + kw];
                best = fmaxf(best, s);
            }
        op[co] = fmaxf(best + bs[c0 + co], 0.f);
    }
}

// big conv: 128x128 tile, 8x8 micro, f32x2 packed FMA (round-14 form)
__global__ void __launch_bounds__(256) k_conv128(const float* __restrict__ in,
        const float* __restrict__ wt, const float* __restrict__ bias,
        float* __restrict__ out, int H, int W, int Cin, int Cout) {
    __shared__ float As[16][132];
    __shared__ float Bs[16][132];
    int bm = blockIdx.y << 7, bn = blockIdx.x << 7, tid = threadIdx.x;
    int lm = tid >> 1, kh8 = (tid & 1) << 3;
    int m = bm + lm;
    int wq = m % W; int tmp = m / W; int hq = tmp % H; int nq = tmp / H;
    int bkk = tid >> 5, bkn = (tid & 31) << 2;
    int cr = (tid >> 4) << 3, cc = (tid & 15) << 3;
    u64 acc2[4][8];
#pragma unroll
    for (int i = 0; i < 4; i++)
#pragma unroll
        for (int j = 0; j < 8; j++) acc2[i][j] = pk2(0.f, 0.f);
    for (int kh = 0; kh < 3; kh++) {
        int ih = hq + kh - 1;
        for (int kw = 0; kw < 3; kw++) {
            int iw = wq + kw - 1;
            bool ok = (ih >= 0) && (ih < H) && (iw >= 0) && (iw < W);
            const float* ibase = in + (((size_t)nq * H + ih) * W + iw) * Cin + kh8;
            const float* wbase = wt + (size_t)(kh * 3 + kw) * Cin * Cout + bn + bkn;
            for (int c0 = 0; c0 < Cin; c0 += 16) {
                float4 a0 = ok ? *(const float4*)(ibase + c0)
                               : make_float4(0.f, 0.f, 0.f, 0.f);
                float4 a1 = ok ? *(const float4*)(ibase + c0 + 4)
                               : make_float4(0.f, 0.f, 0.f, 0.f);
                As[kh8 + 0][lm] = a0.x; As[kh8 + 1][lm] = a0.y;
                As[kh8 + 2][lm] = a0.z; As[kh8 + 3][lm] = a0.w;
                As[kh8 + 4][lm] = a1.x; As[kh8 + 5][lm] = a1.y;
                As[kh8 + 6][lm] = a1.z; As[kh8 + 7][lm] = a1.w;
                *(float4*)&Bs[bkk][bkn] =
                    *(const float4*)(wbase + (size_t)(c0 + bkk) * Cout);
                *(float4*)&Bs[bkk + 8][bkn] =
                    *(const float4*)(wbase + (size_t)(c0 + bkk + 8) * Cout);
                __syncthreads();
#pragma unroll
                for (int kk = 0; kk < 16; kk++) {
                    float4 av0 = *(const float4*)&As[kk][cr];
                    float4 av1 = *(const float4*)&As[kk][cr + 4];
                    u64 ap[4] = { pk2(av0.x, av0.y), pk2(av0.z, av0.w),
                                  pk2(av1.x, av1.y), pk2(av1.z, av1.w) };
                    float4 b0 = *(const float4*)&Bs[kk][cc];
                    float4 b1 = *(const float4*)&Bs[kk][cc + 4];
                    u64 bd[8] = { pk2(b0.x, b0.x), pk2(b0.y, b0.y), pk2(b0.z, b0.z),
                                  pk2(b0.w, b0.w), pk2(b1.x, b1.x), pk2(b1.y, b1.y),
                                  pk2(b1.z, b1.z), pk2(b1.w, b1.w) };
#pragma unroll
                    for (int ip = 0; ip < 4; ip++)
#pragma unroll
                        for (int j = 0; j < 8; j++) fm2(acc2[ip][j], ap[ip], bd[j]);
                }
                __syncthreads();
            }
        }
    }
#pragma unroll
    for (int ip = 0; ip < 4; ip++) {
        float* op0 = &out[(size_t)(bm + cr + 2 * ip) * Cout + bn + cc];
        float* op1 = op0 + Cout;
#pragma unroll
        for (int j = 0; j < 8; j++) {
            float2 v = up2(acc2[ip][j]);
            float bb = bias[bn + cc + j];
            op0[j] = fmaxf(v.x + bb, 0.f);
            op1[j] = fmaxf(v.y + bb, 0.f);
        }
    }
}

// big GEMM: C = A@B (+bias). 128x128 tile, f32x2 (round-14 form)
__global__ void __launch_bounds__(256) k_gemm128(const float* __restrict__ A,
        const float* __restrict__ B, const float* __restrict__ bias,
        float* __restrict__ C, int N, int K) {
    __shared__ float As[16][132];
    __shared__ float Bs[16][132];
    int bm = blockIdx.y << 7, bn = blockIdx.x << 7, tid = threadIdx.x;
    int lm = tid >> 1, kh8 = (tid & 1) << 3;
    int bkk = tid >> 5, bkn = (tid & 31) << 2;
    int cr = (tid >> 4) << 3, cc = (tid & 15) << 3;
    const float* arow = A + (size_t)(bm + lm) * K + kh8;
    const float* bcol = B + bn + bkn;
    u64 acc2[4][8];
#pragma unroll
    for (int i = 0; i < 4; i++)
#pragma unroll
        for (int j = 0; j < 8; j++) acc2[i][j] = pk2(0.f, 0.f);
    for (int k0 = 0; k0 < K; k0 += 16) {
        float4 a0 = *(const float4*)(arow + k0);
        float4 a1 = *(const float4*)(arow + k0 + 4);
        As[kh8 + 0][lm] = a0.x; As[kh8 + 1][lm] = a0.y;
        As[kh8 + 2][lm] = a0.z; As[kh8 + 3][lm] = a0.w;
        As[kh8 + 4][lm] = a1.x; As[kh8 + 5][lm] = a1.y;
        As[kh8 + 6][lm] = a1.z; As[kh8 + 7][lm] = a1.w;
        *(float4*)&Bs[bkk][bkn] = *(const float4*)(bcol + (size_t)(k0 + bkk) * N);
        *(float4*)&Bs[bkk + 8][bkn] = *(const float4*)(bcol + (size_t)(k0 + bkk + 8) * N);
        __syncthreads();
#pragma unroll
        for (int kk = 0; kk < 16; kk++) {
            float4 av0 = *(const float4*)&As[kk][cr];
            float4 av1 = *(const float4*)&As[kk][cr + 4];
            u64 ap[4] = { pk2(av0.x, av0.y), pk2(av0.z, av0.w),
                          pk2(av1.x, av1.y), pk2(av1.z, av1.w) };
            float4 b0 = *(const float4*)&Bs[kk][cc];
            float4 b1 = *(const float4*)&Bs[kk][cc + 4];
            u64 bd[8] = { pk2(b0.x, b0.x), pk2(b0.y, b0.y), pk2(b0.z, b0.z),
                          pk2(b0.w, b0.w), pk2(b1.x, b1.x), pk2(b1.y, b1.y),
                          pk2(b1.z, b1.z), pk2(b1.w, b1.w) };
#pragma unroll
            for (int ip = 0; ip < 4; ip++)
#pragma unroll
                for (int j = 0; j < 8; j++) fm2(acc2[ip][j], ap[ip], bd[j]);
        }
        __syncthreads();
    }
#pragma unroll
    for (int ip = 0; ip < 4; ip++) {
        float* op0 = &C[(size_t)(bm + cr + 2 * ip) * N + bn + cc];
        float* op1 = op0 + N;
#pragma unroll
        for (int j = 0; j < 8; j++) {
            float2 v = up2(acc2[ip][j]);
            float bb = bias ? bias[bn + cc + j] : 0.f;
            op0[j] = v.x + bb;
            op1[j] = v.y + bb;
        }
    }
}

__global__ void k_pool(const float* __restrict__ in, float* __restrict__ out,
                       int B, int H, int W, int C) {
    int Ho = H >> 1, Wo = W >> 1, c4g = C >> 2;
    int total = B * Ho * Wo * c4g;
    int i = blockIdx.x * 256 + threadIdx.x;
    if (i >= total) return;
    int c4 = (i % c4g) << 2;
    int rem = i / c4g;
    int w = rem % Wo; rem /= Wo;
    int h = rem % Ho; int b = rem / Ho;
    const float* p0 = &in[(((size_t)b * H + 2 * h) * W + 2 * w) * C + c4];
    const float* p1 = p0 + (size_t)W * C;
    float4 a = *(const float4*)p0, b4 = *(const float4*)(p0 + C);
    float4 c = *(const float4*)p1, d = *(const float4*)(p1 + C);
    float4 r;
    r.x = fmaxf(fmaxf(a.x, b4.x), fmaxf(c.x, d.x));
    r.y = fmaxf(fmaxf(a.y, b4.y), fmaxf(c.y, d.y));
    r.z = fmaxf(fmaxf(a.z, b4.z), fmaxf(c.z, d.z));
    r.w = fmaxf(fmaxf(a.w, b4.w), fmaxf(c.w, d.w));
    *(float4*)&out[(((size_t)b * Ho + h) * Wo + w) * C + c4] = r;
}

__global__ void k_make_rows() {
    int i = blockIdx.x * 256 + threadIdx.x;
    if (i >= 1048576) return;
    int c4 = (i & 127) << 2;
    int m = i >> 7;
    int n = m >> 6, wp = m & 63;
    *(float4*)&g_rows[((size_t)wp * 128 + n) * 512 + c4] =
        *(const float4*)&g_pool4[(size_t)m * 512 + c4];
}

// persistent bidirectional LSTM: 128 units (8 rows each) = 1 wave per step
__global__ void __launch_bounds__(256) k_lstm_all(const float* __restrict__ Wfw,
                                                  const float* __restrict__ Wbw) {
    __shared__ float Hs[256][9];
    __shared__ float Zs[4][8][64];
    int t = threadIdx.x;
    for (int s = 0; s < 64; s++) {
        for (int vb = blockIdx.x; vb < 128; vb += gridDim.x) {
            int dir = vb >> 6, rg = (vb >> 2) & 15, dg = vb & 3;
            const float* W = dir ? Wbw : Wfw;
            int tx = dir ? (63 - s) : s;
            int n0 = rg << 3;
            int dl = t & 63, g = t >> 6;
            int d = (dg << 6) + dl;
            float a[8];
#pragma unroll
            for (int r = 0; r < 8; r++) a[r] = 0.f;
            if (s > 0) {
                int txp = dir ? (64 - s) : (s - 1);
                const float* hprev = &g_hs[dir][(size_t)txp * 32768];
                for (int i = t; i < 2048; i += 256) {
                    int r = i >> 8, k = i & 255;
                    Hs[k][r] = hprev[(n0 + r) * 256 + k];
                }
                __syncthreads();
                const float* wp = &W[(size_t)512 * 1024 + g * 256 + d];
#pragma unroll 8
                for (int k = 0; k < 256; k++) {
                    float w = wp[(size_t)k * 1024];
#pragma unroll
                    for (int r = 0; r < 8; r++) a[r] += Hs[k][r] * w;
                }
            }
#pragma unroll
            for (int r = 0; r < 8; r++) Zs[g][r][dl] = a[r];
            __syncthreads();
            for (int idx = t; idx < 512; idx += 256) {
                int r = idx >> 6, dl2 = idx & 63;
                int dd = (dg << 6) + dl2;
                const float* pre = &g_pre[dir][((size_t)tx * 128 + n0 + r) * 1024];
                float zi = Zs[0][r][dl2] + pre[dd];
                float zj = Zs[1][r][dl2] + pre[256 + dd];
                float zf = Zs[2][r][dl2] + pre[512 + dd];
                float zo = Zs[3][r][dl2] + pre[768 + dd];
                int ci = (n0 + r) * 256 + dd;
                float c = g_cenc[dir][ci];
                c = sigm(zf + 1.f) * c + sigm(zi) * tanh_(zj);
                g_cenc[dir][ci] = c;
                g_hs[dir][(size_t)tx * 32768 + ci] = sigm(zo) * tanh_(c);
            }
            __syncthreads();
        }
        gridbar();
    }
}

__global__ void k_make_memory() {
    int i = blockIdx.x * 256 + threadIdx.x;
    if (i >= 1048576) return;
    int c4 = (i & 127) << 2;
    int li = i >> 7;
    int b = li >> 9, l = li & 511;
    int hp = l >> 6, wp = l & 63;
    int n = b * 8 + hp;
    float4 v = (c4 < 256)
        ? *(const float4*)&g_hs[0][((size_t)wp * 128 + n) * 256 + c4]
        : *(const float4*)&g_hs[1][((size_t)wp * 128 + n) * 256 + (c4 - 256)];
    *(float4*)&g_memory[(size_t)li * 512 + c4] = v;
}

// persistent decoder: 150 steps, 4 gridbars/step
__global__ void __launch_bounds__(256) k_decoder(
    const float* __restrict__ emb, const int* __restrict__ labels,
    const float* __restrict__ bdec, const float* __restrict__ Wq,
    const float* __restrict__ v_att, const float* __restrict__ bout,
    float* __restrict__ out) {
    __shared__ float sp[2304];
    int tid = threadIdx.x;
    for (int st = 0; st <= 150; st++) {
        int hp = (st + 1) & 1;
        // ---- slot A: P1 z partials (128u) || P7a logits partial (16u) ----
        for (int vb = blockIdx.x; vb < 144; vb += gridDim.x) {
            if (vb < 128) {
                if (st >= 150) continue;
                int cb = vb & 7, kc = vb >> 3, k0 = kc * 69;
                for (int i = tid; i < 1104; i += 256) {
                    int r = i / 69, k = i - r * 69;
                    int kg = k0 + k;
                    float v;
                    if (kg < 80) v = emb[labels[r * 151 + st] * 80 + kg];
                    else if (kg < 592) v = g_ctx[r * 512 + (kg - 80)];
                    else v = g_h2[hp * 8192 + r * 512 + (kg - 592)];
                    sp[r * 72 + k] = v;
                }
                __syncthreads();
                int c0 = cb * 256 + (tid & 63) * 4;
                int rg = tid >> 6;
                float acc[4][4] = {};
#pragma unroll 16
                for (int kk = 0; kk < 69; kk++) {
                    float4 w = *(const float4*)&g_wdecF[(size_t)(k0 + kk) * 2048 + c0];
#pragma unroll
                    for (int r = 0; r < 4; r++) {
                        float x = sp[(rg * 4 + r) * 72 + kk];
                        acc[r][0] += x * w.x; acc[r][1] += x * w.y;
                        acc[r][2] += x * w.z; acc[r][3] += x * w.w;
                    }
                }
#pragma unroll
                for (int r = 0; r < 4; r++)
                    *(float4*)&g_zpart[(size_t)(kc * 16 + rg * 4 + r) * 2048 + c0] =
                        make_float4(acc[r][0], acc[r][1], acc[r][2], acc[r][3]);
                __syncthreads();
            } else if (st >= 1) {
                int u = vb - 128;
                int cb = u & 1, kc = u >> 1, k0 = kc * 128;
                for (int i = tid; i < 2048; i += 256) {
                    int r = i >> 7, k = i & 127;
                    int kg = k0 + k;
                    float v = (kg < 512) ? g_h2[hp * 8192 + r * 512 + kg]
                                         : g_ctx[r * 512 + (kg - 512)];
                    sp[r * 132 + k] = v;
                }
                __syncthreads();
                int c0 = cb * 256 + (tid & 63) * 4;
                int rg = tid >> 6;
                float acc[4][4] = {};
#pragma unroll 16
                for (int kk = 0; kk < 128; kk++) {
                    float4 w = *(const float4*)&g_wlogF[(size_t)(k0 + kk) * 512 + c0];
#pragma unroll
                    for (int r = 0; r < 4; r++) {
                        float x = sp[(rg * 4 + r) * 132 + kk];
                        acc[r][0] += x * w.x; acc[r][1] += x * w.y;
                        acc[r][2] += x * w.z; acc[r][3] += x * w.w;
                    }
                }
#pragma unroll
                for (int r = 0; r < 4; r++)
                    *(float4*)&g_lpart[(size_t)(kc * 16 + rg * 4 + r) * 512 + c0] =
                        make_float4(acc[r][0], acc[r][1], acc[r][2], acc[r][3]);
                __syncthreads();
            }
        }
        gridbar();
        // ---- slot B: P2 gates+h+qpart (64u: b x quarter of 128 d) ----
        if (st < 150) {
            for (int vb = blockIdx.x; vb < 64; vb += gridDim.x) {
                int b = vb >> 2, q = vb & 3, d0 = q * 128;
                if (tid < 128) {
                    int d = d0 + tid;
                    float zi = bdec[d], zj = bdec[512 + d], zf = bdec[1024 + d], zo = bdec[1536 + d];
#pragma unroll
                    for (int p = 0; p < 16; p++) {
                        const float* zp = &g_zpart[(size_t)(p * 16 + b) * 2048];
                        zi += zp[d]; zj += zp[512 + d]; zf += zp[1024 + d]; zo += zp[1536 + d];
                    }
                    float c = g_cdec[b * 512 + d];
                    c = sigm(zf + 1.f) * c + sigm(zi) * tanh_(zj);
                    float h = sigm(zo) * tanh_(c);
                    g_cdec[b * 512 + d] = c;
                    g_h2[(st & 1) * 8192 + b * 512 + d] = h;
                    sp[tid] = h;
                }
                __syncthreads();
                // qpart[q][b,:] = h_slice @ Wq[d0..d0+128, :], 2-way splitK
                int c4 = (tid & 127) * 4, kh = tid >> 7;
                float4 a = make_float4(0.f, 0.f, 0.f, 0.f);
#pragma unroll 16
                for (int kk = 0; kk < 64; kk++) {
                    int kl = kh * 64 + kk;
                    float x = sp[kl];
                    float4 w = *(const float4*)&Wq[(size_t)(d0 + kl) * 512 + c4];
                    a.x += x * w.x; a.y += x * w.y; a.z += x * w.z; a.w += x * w.w;
                }
                *(float4*)&sp[256 + kh * 512 + c4] = a;
                __syncthreads();
                int base = (q * 16 + b) * 512;
                g_qpart2[base + tid] = sp[256 + tid] + sp[256 + 512 + tid];
                g_qpart2[base + 256 + tid] = sp[256 + 256 + tid] + sp[256 + 768 + tid];
                __syncthreads();
            }
        }
        gridbar();
        // ---- slot C: P4 scores (128u, tanh.approx) || P7b logits out (8u) ----
        for (int vb = blockIdx.x; vb < 136; vb += gridDim.x) {
            if (vb < 128) {
                if (st >= 150) continue;
                int b = vb >> 3, lg = vb & 7;
                for (int i = tid; i < 512; i += 256) {
                    sp[i] = g_qpart2[b * 512 + i] + g_qpart2[(16 + b) * 512 + i]
                          + g_qpart2[(32 + b) * 512 + i] + g_qpart2[(48 + b) * 512 + i];
                    sp[512 + i] = v_att[i];
                }
                __syncthreads();
                int w = tid >> 5, lane = tid & 31;
#pragma unroll
                for (int j = 0; j < 8; j++) {
                    int l = lg * 64 + w * 8 + j;
                    const float* kp = &g_keys[((size_t)b * 512 + l) * 512];
                    float acc = 0.f;
#pragma unroll
                    for (int it = 0; it < 4; it++) {
                        int d = it * 128 + lane * 4;
                        float4 kv = *(const float4*)&kp[d];
                        acc += tanha(kv.x + sp[d]) * sp[512 + d]
                             + tanha(kv.y + sp[d + 1]) * sp[512 + d + 1]
                             + tanha(kv.z + sp[d + 2]) * sp[512 + d + 2]
                             + tanha(kv.w + sp[d + 3]) * sp[512 + d + 3];
                    }
#pragma unroll
                    for (int off = 16; off; off >>= 1) acc += __shfl_down_sync(0xffffffffu, acc, off);
                    if (lane == 0) g_scores[b * 512 + l] = acc;
                }
                __syncthreads();
            } else if (st >= 1) {
                int u = vb - 128;
                if (tid < 252) {
                    int cl = tid % 63, rg = tid / 63;
                    int c = u * 63 + cl;
#pragma unroll
                    for (int i = 0; i < 4; i++) {
                        int b = rg * 4 + i;
                        float s = bout[c];
#pragma unroll
                        for (int p = 0; p < 8; p++) s += g_lpart[(p * 16 + b) * 512 + c];
                        out[((size_t)b * 150 + (st - 1)) * 504 + c] = s;
                    }
                }
            }
        }
        gridbar();
        // ---- slot D: P5 softmax + FINAL ctx (64u: b x quarter) ----
        if (st < 150) {
            for (int vb = blockIdx.x; vb < 64; vb += gridDim.x) {
                int b = vb >> 2, q4 = vb & 3;
                float* sc = sp;            // 512
                float* red = sp + 512;     // 256
                float* al = sp + 768;      // 512
                float* Zs = sp + 1280;     // 8 x 128
                sc[tid] = g_scores[b * 512 + tid];
                sc[tid + 256] = g_scores[b * 512 + 256 + tid];
                __syncthreads();
                float m = fmaxf(sc[tid], sc[tid + 256]);
                red[tid] = m; __syncthreads();
                for (int s = 128; s; s >>= 1) {
                    if (tid < s) red[tid] = fmaxf(red[tid], red[tid + s]);
                    __syncthreads();
                }
                m = red[0]; __syncthreads();
                float e0 = __expf(sc[tid] - m), e1 = __expf(sc[tid + 256] - m);
                red[tid] = e0 + e1;
                __syncthreads();
                for (int s = 128; s; s >>= 1) {
                    if (tid < s) red[tid] += red[tid + s];
                    __syncthreads();
                }
                float inv = __fdividef(1.f, red[0]);
                __syncthreads();
                al[tid] = e0 * inv; al[tid + 256] = e1 * inv;
                __syncthreads();
                {
                    int rg = tid >> 5;                    // 0..7, 64 l each
                    int c = q4 * 128 + (tid & 31) * 4;    // 128 cols
                    float4 a = make_float4(0.f, 0.f, 0.f, 0.f);
                    const float* mp = &g_memory[((size_t)b * 512 + rg * 64) * 512 + c];
#pragma unroll 16
                    for (int l = 0; l < 64; l++) {
                        float av = al[rg * 64 + l];
                        float4 mv = *(const float4*)(mp + (size_t)l * 512);
                        a.x += av * mv.x; a.y += av * mv.y;
                        a.z += av * mv.z; a.w += av * mv.w;
                    }
                    *(float4*)&Zs[rg * 128 + (tid & 31) * 4] = a;
                }
                __syncthreads();
                if (tid < 128) {
                    float s = 0.f;
#pragma unroll
                    for (int r = 0; r < 8; r++) s += Zs[r * 128 + tid];
                    g_ctx[b * 512 + q4 * 128 + tid] = s;
                }
                __syncthreads();
            }
        }
        gridbar();
    }
}

extern "C" void kernel_launch(void* const* d_in, const int* in_sizes, int n_in,
                              void* d_out, int out_size) {
    (void)in_sizes; (void)out_size;
    int o = n_in - 21;
    const float* inp    = (const float*)d_in[0];
    const int*   labels = (const int*)d_in[1];
    const float* ck1 = (const float*)d_in[o + 0];  const float* cb1 = (const float*)d_in[o + 1];
    const float* ck2 = (const float*)d_in[o + 2];  const float* cb2 = (const float*)d_in[o + 3];
    const float* ck3 = (const float*)d_in[o + 4];  const float* cb3 = (const float*)d_in[o + 5];
    const float* ck4 = (const float*)d_in[o + 6];  const float* cb4 = (const float*)d_in[o + 7];
    const float* Wfw = (const float*)d_in[o + 8];  const float* bfw = (const float*)d_in[o + 9];
    const float* Wbw = (const float*)d_in[o + 10]; const float* bbw = (const float*)d_in[o + 11];
    const float* Wdec = (const float*)d_in[o + 12]; const float* bdec = (const float*)d_in[o + 13];
    const float* Wmem = (const float*)d_in[o + 14]; const float* Wq   = (const float*)d_in[o + 15];
    const float* v_att = (const float*)d_in[o + 16]; const float* Wattn = (const float*)d_in[o + 17];
    const float* Wout = (const float*)d_in[o + 18]; const float* bout = (const float*)d_in[o + 19];
    const float* emb  = (const float*)d_in[o + 20];
    float* out = (float*)d_out;

    void *a_, *b_, *p4_, *r_, *pre_, *mem_, *keys_, *wf_, *wl_, *wp_;
    cudaGetSymbolAddress(&a_, g_bufA);
    cudaGetSymbolAddress(&b_, g_bufB);
    cudaGetSymbolAddress(&p4_, g_pool4);
    cudaGetSymbolAddress(&r_, g_rows);
    cudaGetSymbolAddress(&pre_, g_pre);
    cudaGetSymbolAddress(&mem_, g_memory);
    cudaGetSymbolAddress(&keys_, g_keys);
    cudaGetSymbolAddress(&wf_, g_wdecF);
    cudaGetSymbolAddress(&wl_, g_wlogF);
    cudaGetSymbolAddress(&wp_, g_woutP);
    float* pA = (float*)a_; float* pB = (float*)b_;
    float* pP4 = (float*)p4_; float* pR = (float*)r_;
    float* pPre0 = (float*)pre_; float* pPre1 = pPre0 + 8388608;
    float* pMem = (float*)mem_; float* pKeys = (float*)keys_;
    float* pWdecF = (float*)wf_; float* pWlogF = (float*)wl_;
    float* pWoutP = (float*)wp_;

    cudaMemcpyAsync(pWdecF, Wdec, (size_t)80 * 2048 * sizeof(float),
                    cudaMemcpyDeviceToDevice);
    k_padW<<<1024, 256>>>(Wout);
    k_gemm64<<<dim3(32, 8), 256>>>(Wattn + 512 * 512, Wdec + 80 * 2048,
        (const float*)0, pWdecF + 80 * 2048, 2048, 512);
    k_gemm64<<<dim3(32, 8), 256>>>(Wattn, Wdec + 80 * 2048,
        Wdec + (size_t)592 * 2048, pWdecF + (size_t)592 * 2048, 2048, 512);
    k_gemm64<<<dim3(8, 16), 256>>>(Wattn, pWoutP,
        (const float*)0, pWlogF, 512, 512);

    k_init<<<256, 256>>>();
    k_conv1pool<<<2048, 256>>>(inp, ck1, cb1, pB);
    k_conv128<<<dim3(1, 1024), 256>>>(pB, ck2, cb2, pA, 32, 256, 64, 128);
    k_pool<<<4096, 256>>>(pA, pB, 16, 32, 256, 128);
    k_conv128<<<dim3(2, 256), 256>>>(pB, ck3, cb3, pA, 16, 128, 128, 256);
    k_conv128<<<dim3(4, 256), 256>>>(pA, ck4, cb4, pB, 16, 128, 256, 512);
    k_pool<<<4096, 256>>>(pB, pP4, 16, 16, 128, 512);
    k_make_rows<<<4096, 256>>>();
    k_gemm128<<<dim3(8, 64), 256>>>(pR, Wfw, bfw, pPre0, 1024, 512);
    k_gemm128<<<dim3(8, 64), 256>>>(pR, Wbw, bbw, pPre1, 1024, 512);
    k_lstm_all<<<148, 256>>>(Wfw, Wbw);
    k_make_memory<<<4096, 256>>>();
    k_gemm128<<<dim3(4, 64), 256>>>(pMem, Wmem, (const float*)0, pKeys, 512, 512);
    k_decoder<<<148, 256>>>(emb, labels, bdec, Wq, v_att, bout, out);
}